// round 1
// baseline (speedup 1.0000x reference)
#include <cuda_runtime.h>
#include <cuda_bf16.h>

// WTConv2d: 3-level Haar wavelet transform + depthwise 5x5 convs + inverse.
// B=8, C=96, H=W=224, K=5, L=3.  All fp32.
//
// Pipeline:
//   fwd0: x(224) -> haar -> dwconv4 -> coeff0(112) ; raw LL1(112)
//   fwd1: LL1    -> haar -> dwconv4 -> coeff1(56)  ; raw LL2(56)
//   fwd2: LL2    -> haar -> dwconv4 -> ihaar (next_ll==0) -> add1(56)
//   inv1: coeff1 (LL+=add1) -> ihaar -> add0(112)
//   final: basew dwconv(x)*scale+bias + ihaar(coeff0, LL+=add0) -> out(224)

#define TILE 16
#define SUBT (TILE + 4)     // 20: subband tile with conv halo (radius 2)
#define INTL (2 * SUBT)     // 40: input tile

// ---- scratch (static device memory; no allocations allowed) ----
__device__ float g_coeff0[8 * 96 * 4 * 112 * 112];  // 154 MB
__device__ float g_coeff1[8 * 96 * 4 * 56 * 56];    // 38.5 MB
__device__ float g_ll1[8 * 96 * 112 * 112];         // 38.5 MB
__device__ float g_ll2[8 * 96 * 56 * 56];           // 9.6 MB
__device__ float g_add1[8 * 96 * 56 * 56];          // 9.6 MB
__device__ float g_add0[8 * 96 * 112 * 112];        // 38.5 MB

// Forward level: haar2d of (2h x 2w) input + depthwise 5x5 SAME conv (zero pad
// in subband domain) + per-channel scale. Optionally writes raw LL for the
// next level, or (deepest level) applies ihaar directly instead of storing
// coefficients.
template <bool WRITE_LL, bool IHAAR>
__global__ __launch_bounds__(256) void fwd_kernel(
    const float* __restrict__ in, float* __restrict__ coeff,
    float* __restrict__ ll_out, float* __restrict__ rec_out,
    const float* __restrict__ wts, const float* __restrict__ wsc,
    int C, int h, int w)
{
    __shared__ float s_in[INTL][INTL + 1];
    __shared__ float s_sub[4][SUBT][SUBT + 1];
    __shared__ float s_w[4][25];
    __shared__ float s_sc[4];

    const int tid = threadIdx.x;
    const int bc = blockIdx.z;
    const int c = bc % C;
    const int w2 = 2 * w, h2 = 2 * h;
    const float* inp = in + (size_t)bc * ((size_t)h2 * w2);
    const int ty0 = blockIdx.y * TILE, tx0 = blockIdx.x * TILE;

    if (tid < 100)
        s_w[tid / 25][tid % 25] = wts[(c * 4 + tid / 25) * 25 + tid % 25];
    else if (tid < 104)
        s_sc[tid - 100] = wsc[c * 4 + (tid - 100)];

    // cooperative coalesced input tile load (zero outside image)
    const int iy0 = 2 * ty0 - 4, ix0 = 2 * tx0 - 4;
    for (int idx = tid; idx < INTL * INTL; idx += 256) {
        int r = idx / INTL, cc = idx % INTL;
        int gy = iy0 + r, gx = ix0 + cc;
        float v = 0.f;
        if (gy >= 0 && gy < h2 && gx >= 0 && gx < w2)
            v = inp[(size_t)gy * w2 + gx];
        s_in[r][cc] = v;
    }
    __syncthreads();

    // haar into 4 subband tiles (zero outside [0,h)x[0,w) = SAME pad)
    for (int idx = tid; idx < SUBT * SUBT; idx += 256) {
        int sy = idx / SUBT, sx = idx % SUBT;
        int gsy = ty0 - 2 + sy, gsx = tx0 - 2 + sx;
        float ll = 0.f, lh = 0.f, hl = 0.f, hh = 0.f;
        if (gsy >= 0 && gsy < h && gsx >= 0 && gsx < w) {
            float a = s_in[2 * sy][2 * sx];
            float b = s_in[2 * sy][2 * sx + 1];
            float cv = s_in[2 * sy + 1][2 * sx];
            float d = s_in[2 * sy + 1][2 * sx + 1];
            ll = (a + b + cv + d) * 0.5f;
            lh = (a - b + cv - d) * 0.5f;
            hl = (a + b - cv - d) * 0.5f;
            hh = (a - b - cv + d) * 0.5f;
        }
        s_sub[0][sy][sx] = ll;
        s_sub[1][sy][sx] = lh;
        s_sub[2][sy][sx] = hl;
        s_sub[3][sy][sx] = hh;
    }
    __syncthreads();

    const int ly = tid >> 4, lx = tid & 15;
    const int oy = ty0 + ly, ox = tx0 + lx;
    if (oy < h && ox < w) {
        float r[4];
#pragma unroll
        for (int s = 0; s < 4; s++) {
            float acc = 0.f;
#pragma unroll
            for (int dy = 0; dy < 5; dy++)
#pragma unroll
                for (int dx = 0; dx < 5; dx++)
                    acc = fmaf(s_sub[s][ly + dy][lx + dx], s_w[s][dy * 5 + dx], acc);
            r[s] = acc * s_sc[s];
        }
        const size_t hw = (size_t)h * w;
        if (!IHAAR) {
            size_t base = ((size_t)bc * 4) * hw + (size_t)oy * w + ox;
            coeff[base] = r[0];
            coeff[base + hw] = r[1];
            coeff[base + 2 * hw] = r[2];
            coeff[base + 3 * hw] = r[3];
        } else {
            float a = (r[0] + r[1] + r[2] + r[3]) * 0.5f;
            float b = (r[0] - r[1] + r[2] - r[3]) * 0.5f;
            float cv = (r[0] + r[1] - r[2] - r[3]) * 0.5f;
            float d = (r[0] - r[1] - r[2] + r[3]) * 0.5f;
            float* outp = rec_out + (size_t)bc * 4 * hw;
            *(float2*)(outp + (size_t)(2 * oy) * w2 + 2 * ox) = make_float2(a, b);
            *(float2*)(outp + (size_t)(2 * oy + 1) * w2 + 2 * ox) = make_float2(cv, d);
        }
        if (WRITE_LL)
            ll_out[(size_t)bc * hw + (size_t)oy * w + ox] = s_sub[0][ly + 2][lx + 2];
    }
}

// inverse haar of stored coefficients, with next_ll added to the LL band
__global__ __launch_bounds__(256) void inv_kernel(
    const float* __restrict__ coeff, const float* __restrict__ addend,
    float* __restrict__ out, int h, int w, int total)
{
    int idx = blockIdx.x * 256 + threadIdx.x;
    if (idx >= total) return;
    const int hw = h * w;
    int bc = idx / hw;
    int i = idx - bc * hw;
    int y = i / w, x = i - y * w;
    size_t base = ((size_t)bc * 4) * hw + i;
    float ll = coeff[base] + addend[(size_t)bc * hw + i];
    float lh = coeff[base + hw];
    float hl = coeff[base + 2 * (size_t)hw];
    float hh = coeff[base + 3 * (size_t)hw];
    float a = (ll + lh + hl + hh) * 0.5f;
    float b = (ll - lh + hl - hh) * 0.5f;
    float cv = (ll + lh - hl - hh) * 0.5f;
    float d = (ll - lh - hl + hh) * 0.5f;
    float* outp = out + (size_t)bc * 4 * (size_t)hw;
    int w2 = 2 * w;
    *(float2*)(outp + (size_t)(2 * y) * w2 + 2 * x) = make_float2(a, b);
    *(float2*)(outp + (size_t)(2 * y + 1) * w2 + 2 * x) = make_float2(cv, d);
}

// final: base depthwise conv on x (scale+bias) + ihaar of level-0 coeffs
__global__ __launch_bounds__(256) void final_kernel(
    const float* __restrict__ x, const float* __restrict__ coeff0,
    const float* __restrict__ add0, const float* __restrict__ bw,
    const float* __restrict__ bscale, const float* __restrict__ bb,
    float* __restrict__ out, int C, int H, int W)
{
    __shared__ float s_in[TILE + 4][TILE + 5];
    __shared__ float s_w[25];
    __shared__ float s_p[2];

    const int tid = threadIdx.x;
    const int bc = blockIdx.z;
    const int c = bc % C;
    const int ty0 = blockIdx.y * TILE, tx0 = blockIdx.x * TILE;
    const float* inp = x + (size_t)bc * H * W;

    if (tid < 25) s_w[tid] = bw[c * 25 + tid];
    else if (tid == 25) s_p[0] = bscale[c];
    else if (tid == 26) s_p[1] = bb[c];

    for (int idx = tid; idx < (TILE + 4) * (TILE + 4); idx += 256) {
        int r = idx / (TILE + 4), cc = idx % (TILE + 4);
        int gy = ty0 - 2 + r, gx = tx0 - 2 + cc;
        s_in[r][cc] = (gy >= 0 && gy < H && gx >= 0 && gx < W)
                          ? inp[(size_t)gy * W + gx] : 0.f;
    }
    __syncthreads();

    const int ly = tid >> 4, lx = tid & 15;
    const int oy = ty0 + ly, ox = tx0 + lx;  // H,W divisible by TILE

    float acc = 0.f;
#pragma unroll
    for (int dy = 0; dy < 5; dy++)
#pragma unroll
        for (int dx = 0; dx < 5; dx++)
            acc = fmaf(s_in[ly + dy][lx + dx], s_w[dy * 5 + dx], acc);

    const int w2 = W >> 1;
    const int sy = oy >> 1, sx = ox >> 1;
    const size_t hw = (size_t)(H >> 1) * w2;
    const size_t cb = ((size_t)bc * 4) * hw + (size_t)sy * w2 + sx;
    float ll = coeff0[cb] + add0[(size_t)bc * hw + (size_t)sy * w2 + sx];
    float lh = coeff0[cb + hw];
    float hl = coeff0[cb + 2 * hw];
    float hh = coeff0[cb + 3 * hw];
    float slh = (ox & 1) ? -1.f : 1.f;
    float shl = (oy & 1) ? -1.f : 1.f;
    float rec = 0.5f * (ll + slh * lh + shl * hl + slh * shl * hh);

    out[(size_t)bc * H * W + (size_t)oy * W + ox] = acc * s_p[0] + s_p[1] + rec;
}

extern "C" void kernel_launch(void* const* d_in, const int* in_sizes, int n_in,
                              void* d_out, int out_size)
{
    const float* x          = (const float*)d_in[0];
    const float* base_w     = (const float*)d_in[1];
    const float* base_b     = (const float*)d_in[2];
    const float* base_scale = (const float*)d_in[3];
    const float* wconv_w    = (const float*)d_in[4];
    const float* wscale     = (const float*)d_in[5];
    float* out = (float*)d_out;

    const int B = 8, C = 96;
    const int BC = B * C;

    void *p0, *p1, *p2, *p3, *p4, *p5;
    cudaGetSymbolAddress(&p0, g_coeff0);
    cudaGetSymbolAddress(&p1, g_coeff1);
    cudaGetSymbolAddress(&p2, g_ll1);
    cudaGetSymbolAddress(&p3, g_ll2);
    cudaGetSymbolAddress(&p4, g_add1);
    cudaGetSymbolAddress(&p5, g_add0);
    float* coeff0 = (float*)p0;
    float* coeff1 = (float*)p1;
    float* ll1    = (float*)p2;
    float* ll2    = (float*)p3;
    float* add1   = (float*)p4;
    float* add0   = (float*)p5;

    // level 0: x(224) -> coeff0(112) + ll1(112)
    {
        dim3 grid((112 + TILE - 1) / TILE, (112 + TILE - 1) / TILE, BC);
        fwd_kernel<true, false><<<grid, 256>>>(
            x, coeff0, ll1, nullptr,
            wconv_w + 0 * 4 * C * 25, wscale + 0 * 4 * C, C, 112, 112);
    }
    // level 1: ll1(112) -> coeff1(56) + ll2(56)
    {
        dim3 grid((56 + TILE - 1) / TILE, (56 + TILE - 1) / TILE, BC);
        fwd_kernel<true, false><<<grid, 256>>>(
            ll1, coeff1, ll2, nullptr,
            wconv_w + 1 * 4 * C * 25, wscale + 1 * 4 * C, C, 56, 56);
    }
    // level 2 fwd + inverse fused (next_ll == 0): ll2(56) -> add1(56)
    {
        dim3 grid((28 + TILE - 1) / TILE, (28 + TILE - 1) / TILE, BC);
        fwd_kernel<false, true><<<grid, 256>>>(
            ll2, nullptr, nullptr, add1,
            wconv_w + 2 * 4 * C * 25, wscale + 2 * 4 * C, C, 28, 28);
    }
    // inverse level 1: coeff1 (LL += add1) -> add0(112)
    {
        int total = BC * 56 * 56;
        inv_kernel<<<(total + 255) / 256, 256>>>(coeff1, add1, add0, 56, 56, total);
    }
    // final: base conv + ihaar(coeff0, LL += add0) -> out(224)
    {
        dim3 grid(224 / TILE, 224 / TILE, BC);
        final_kernel<<<grid, 256>>>(x, coeff0, add0, base_w, base_scale,
                                    base_b, out, C, 224, 224);
    }
}

// round 2
// speedup vs baseline: 1.6771x; 1.6771x over previous
#include <cuda_runtime.h>
#include <cuda_bf16.h>

// WTConv2d: 3-level Haar + depthwise 5x5 + inverse.  B=8,C=96,H=W=224,K=5.
// Round 2: LDS-optimized. Weights in registers, register-tiled conv with
// conflict-free LDS.128, vectorized global I/O.

#define TX 16
#define TY 16
#define SUBW 20      // TY+4 (= TX+4)
#define SUBPAD 48    // row pad: 192B -> rows 128B-offset by 64 -> LDS.128 conflict-free
#define INR 40       // 2*SUBW
#define INC 40
#define INPAD 42

// ---- scratch (static device memory) ----
__device__ float g_coeff0[8 * 96 * 4 * 112 * 112];
__device__ float g_coeff1[8 * 96 * 4 * 56 * 56];
__device__ float g_ll1[8 * 96 * 112 * 112];
__device__ float g_ll2[8 * 96 * 56 * 56];
__device__ float g_add1[8 * 96 * 56 * 56];
__device__ float g_add0[8 * 96 * 112 * 112];

// Forward level: haar2d of (2h x 2w) input + depthwise 5x5 SAME conv + scale.
// One subband per thread-group of 64; each thread: 1 row x 4 outputs.
template <bool WRITE_LL, bool IHAAR>
__global__ __launch_bounds__(256) void fwd_kernel(
    const float* __restrict__ in, float* __restrict__ coeff,
    float* __restrict__ ll_out, float* __restrict__ rec_out,
    const float* __restrict__ wts, const float* __restrict__ wsc,
    int C, int h, int w)
{
    __shared__ float s_in[INR][INPAD];
    __shared__ float s_sub[4][SUBW][SUBPAD];

    const int tid = threadIdx.x;
    const int bc = blockIdx.z;
    const int c = bc % C;
    const int w2 = 2 * w, h2 = 2 * h;
    const float* inp = in + (size_t)bc * ((size_t)h2 * w2);
    const int ty0 = blockIdx.y * TY, tx0 = blockIdx.x * TX;

    // per-thread weights (one subband per thread)
    const int s  = tid >> 6;
    const int r  = (tid & 63) >> 2;
    const int xg = tid & 3;
    float wv[25];
#pragma unroll
    for (int j = 0; j < 25; j++) wv[j] = __ldg(&wts[(c * 4 + s) * 25 + j]);
    const float sc = __ldg(&wsc[c * 4 + s]);

    // input tile load (float2, zero pad)
    const int iy0 = 2 * ty0 - 4, ix0 = 2 * tx0 - 4;
    for (int idx = tid; idx < INR * (INC / 2); idx += 256) {
        int rr = idx / (INC / 2), cp = idx % (INC / 2);
        int gy = iy0 + rr, gx = ix0 + 2 * cp;
        float2 v = make_float2(0.f, 0.f);
        if (gy >= 0 && gy < h2 && gx >= 0 && gx < w2)
            v = *(const float2*)(inp + (size_t)gy * w2 + gx);
        *(float2*)&s_in[rr][2 * cp] = v;
    }
    __syncthreads();

    // haar -> 4 subband tiles (zero outside [0,h)x[0,w))
    for (int idx = tid; idx < SUBW * SUBW; idx += 256) {
        int sy = idx / SUBW, sx = idx % SUBW;
        int gsy = ty0 - 2 + sy, gsx = tx0 - 2 + sx;
        float ll = 0.f, lh = 0.f, hl = 0.f, hh = 0.f;
        if (gsy >= 0 && gsy < h && gsx >= 0 && gsx < w) {
            float2 t = *(const float2*)&s_in[2 * sy][2 * sx];
            float2 bo = *(const float2*)&s_in[2 * sy + 1][2 * sx];
            ll = (t.x + t.y + bo.x + bo.y) * 0.5f;
            lh = (t.x - t.y + bo.x - bo.y) * 0.5f;
            hl = (t.x + t.y - bo.x - bo.y) * 0.5f;
            hh = (t.x - t.y - bo.x + bo.y) * 0.5f;
        }
        s_sub[0][sy][sx] = ll;
        s_sub[1][sy][sx] = lh;
        s_sub[2][sy][sx] = hl;
        s_sub[3][sy][sx] = hh;
    }
    __syncthreads();

    // depthwise 5x5 conv: 4 outputs per thread along x
    float acc[4] = {0.f, 0.f, 0.f, 0.f};
#pragma unroll
    for (int dy = 0; dy < 5; dy++) {
        float4 p = *(const float4*)&s_sub[s][r + dy][4 * xg];
        float4 q = *(const float4*)&s_sub[s][r + dy][4 * xg + 4];
        float v[8] = {p.x, p.y, p.z, p.w, q.x, q.y, q.z, q.w};
#pragma unroll
        for (int dx = 0; dx < 5; dx++) {
            float wt = wv[5 * dy + dx];
#pragma unroll
            for (int o = 0; o < 4; o++)
                acc[o] = fmaf(v[o + dx], wt, acc[o]);
        }
    }
#pragma unroll
    for (int o = 0; o < 4; o++) acc[o] *= sc;

    const int oy = ty0 + r;
    const int oxb = tx0 + 4 * xg;
    const size_t hw = (size_t)h * w;

    if (!IHAAR) {
        if (oy < h) {
            float* dst = coeff + ((size_t)bc * 4 + s) * hw + (size_t)oy * w + oxb;
            if (oxb + 3 < w) {
                *(float4*)dst = make_float4(acc[0], acc[1], acc[2], acc[3]);
            } else {
#pragma unroll
                for (int o = 0; o < 4; o++)
                    if (oxb + o < w) dst[o] = acc[o];
            }
            if (WRITE_LL && s == 0) {
                float l0 = s_sub[0][r + 2][4 * xg + 2];
                float l1 = s_sub[0][r + 2][4 * xg + 3];
                float l2 = s_sub[0][r + 2][4 * xg + 4];
                float l3 = s_sub[0][r + 2][4 * xg + 5];
                float* ld = ll_out + (size_t)bc * hw + (size_t)oy * w + oxb;
                if (oxb + 3 < w) {
                    *(float4*)ld = make_float4(l0, l1, l2, l3);
                } else {
                    float lv[4] = {l0, l1, l2, l3};
#pragma unroll
                    for (int o = 0; o < 4; o++)
                        if (oxb + o < w) ld[o] = lv[o];
                }
            }
        }
    } else {
        // deepest level: gather 4 subband results per position, ihaar, store
        float* s_conv = &s_in[0][0];  // reuse (4*16*16 floats <= s_in)
        *(float4*)&s_conv[((s * TY) + r) * TX + 4 * xg] =
            make_float4(acc[0], acc[1], acc[2], acc[3]);
        __syncthreads();
        int pr = tid >> 4, px = tid & 15;
        int oy2 = ty0 + pr, ox2 = tx0 + px;
        if (oy2 < h && ox2 < w) {
            float ll = s_conv[(0 * TY + pr) * TX + px];
            float lh = s_conv[(1 * TY + pr) * TX + px];
            float hl = s_conv[(2 * TY + pr) * TX + px];
            float hh = s_conv[(3 * TY + pr) * TX + px];
            float a  = (ll + lh + hl + hh) * 0.5f;
            float b  = (ll - lh + hl - hh) * 0.5f;
            float cv = (ll + lh - hl - hh) * 0.5f;
            float d  = (ll - lh - hl + hh) * 0.5f;
            float* outp = rec_out + (size_t)bc * 4 * hw;
            *(float2*)(outp + (size_t)(2 * oy2) * w2 + 2 * ox2) = make_float2(a, b);
            *(float2*)(outp + (size_t)(2 * oy2 + 1) * w2 + 2 * ox2) = make_float2(cv, d);
        }
    }
}

// inverse haar (2-wide vectorized), LL += addend
__global__ __launch_bounds__(256) void inv_kernel(
    const float* __restrict__ coeff, const float* __restrict__ addend,
    float* __restrict__ out, int h, int w, int total2)
{
    int idx = blockIdx.x * 256 + threadIdx.x;
    if (idx >= total2) return;
    const int wh = w >> 1;
    const int hwp = h * wh;
    int bc = idx / hwp;
    int i = idx - bc * hwp;
    int y = i / wh, xp = i - y * wh;
    const size_t hw = (size_t)h * w;
    const float* base = coeff + ((size_t)bc * 4) * hw + (size_t)y * w + 2 * xp;
    float2 ll = *(const float2*)(base);
    float2 lh = *(const float2*)(base + hw);
    float2 hl = *(const float2*)(base + 2 * hw);
    float2 hh = *(const float2*)(base + 3 * hw);
    float2 ad = *(const float2*)(addend + (size_t)bc * hw + (size_t)y * w + 2 * xp);
    ll.x += ad.x; ll.y += ad.y;
    float a0 = (ll.x + lh.x + hl.x + hh.x) * 0.5f;
    float b0 = (ll.x - lh.x + hl.x - hh.x) * 0.5f;
    float c0 = (ll.x + lh.x - hl.x - hh.x) * 0.5f;
    float d0 = (ll.x - lh.x - hl.x + hh.x) * 0.5f;
    float a1 = (ll.y + lh.y + hl.y + hh.y) * 0.5f;
    float b1 = (ll.y - lh.y + hl.y - hh.y) * 0.5f;
    float c1 = (ll.y + lh.y - hl.y - hh.y) * 0.5f;
    float d1 = (ll.y - lh.y - hl.y + hh.y) * 0.5f;
    float* outp = out + (size_t)bc * 4 * hw;
    const int w22 = 2 * w;
    *(float4*)(outp + (size_t)(2 * y) * w22 + 4 * xp)     = make_float4(a0, b0, a1, b1);
    *(float4*)(outp + (size_t)(2 * y + 1) * w22 + 4 * xp) = make_float4(c0, d0, c1, d1);
}

// final: base depthwise conv + ihaar(coeff0, LL+=add0)
#define FT 32
__global__ __launch_bounds__(256) void final_kernel(
    const float* __restrict__ x, const float* __restrict__ coeff0,
    const float* __restrict__ add0, const float* __restrict__ bw,
    const float* __restrict__ bscale, const float* __restrict__ bb,
    float* __restrict__ out, int C, int H, int W)
{
    __shared__ float s_in[FT + 4][40];

    const int tid = threadIdx.x;
    const int bc = blockIdx.z;
    const int c = bc % C;
    const int ty0 = blockIdx.y * FT, tx0 = blockIdx.x * FT;
    const float* inp = x + (size_t)bc * H * W;

    float wv[25];
#pragma unroll
    for (int j = 0; j < 25; j++) wv[j] = __ldg(&bw[c * 25 + j]);
    const float scl = __ldg(&bscale[c]);
    const float bia = __ldg(&bb[c]);

    for (int idx = tid; idx < 36 * 36; idx += 256) {
        int rr = idx / 36, cc = idx % 36;
        int gy = ty0 - 2 + rr, gx = tx0 - 2 + cc;
        s_in[rr][cc] = (gy >= 0 && gy < H && gx >= 0 && gx < W)
                           ? inp[(size_t)gy * W + gx] : 0.f;
    }
    __syncthreads();

    const int row = tid >> 3;     // 0..31
    const int xg  = tid & 7;      // 0..7
    const int oy  = ty0 + row;
    const int oxb = tx0 + 4 * xg;

    float acc[4] = {0.f, 0.f, 0.f, 0.f};
#pragma unroll
    for (int dy = 0; dy < 5; dy++) {
        float4 p = *(const float4*)&s_in[row + dy][4 * xg];
        float4 q = *(const float4*)&s_in[row + dy][4 * xg + 4];
        float v[8] = {p.x, p.y, p.z, p.w, q.x, q.y, q.z, q.w};
#pragma unroll
        for (int dx = 0; dx < 5; dx++) {
            float wt = wv[5 * dy + dx];
#pragma unroll
            for (int o = 0; o < 4; o++)
                acc[o] = fmaf(v[o + dx], wt, acc[o]);
        }
    }

    const int Wh = W >> 1;
    const int sy = oy >> 1, sx0 = oxb >> 1;
    const size_t hw = (size_t)(H >> 1) * Wh;
    const float* cb = coeff0 + ((size_t)bc * 4) * hw + (size_t)sy * Wh + sx0;
    float2 ll = *(const float2*)cb;
    float2 lh = *(const float2*)(cb + hw);
    float2 hl = *(const float2*)(cb + 2 * hw);
    float2 hh = *(const float2*)(cb + 3 * hw);
    float2 ad = *(const float2*)(add0 + (size_t)bc * hw + (size_t)sy * Wh + sx0);
    ll.x += ad.x; ll.y += ad.y;
    const float shl = (oy & 1) ? -1.f : 1.f;
    float e0 = 0.5f * (ll.x + lh.x + shl * (hl.x + hh.x));
    float e1 = 0.5f * (ll.x - lh.x + shl * (hl.x - hh.x));
    float e2 = 0.5f * (ll.y + lh.y + shl * (hl.y + hh.y));
    float e3 = 0.5f * (ll.y - lh.y + shl * (hl.y - hh.y));

    float4 res;
    res.x = fmaf(acc[0], scl, bia) + e0;
    res.y = fmaf(acc[1], scl, bia) + e1;
    res.z = fmaf(acc[2], scl, bia) + e2;
    res.w = fmaf(acc[3], scl, bia) + e3;
    *(float4*)(out + (size_t)bc * H * W + (size_t)oy * W + oxb) = res;
}

extern "C" void kernel_launch(void* const* d_in, const int* in_sizes, int n_in,
                              void* d_out, int out_size)
{
    const float* x          = (const float*)d_in[0];
    const float* base_w     = (const float*)d_in[1];
    const float* base_b     = (const float*)d_in[2];
    const float* base_scale = (const float*)d_in[3];
    const float* wconv_w    = (const float*)d_in[4];
    const float* wscale     = (const float*)d_in[5];
    float* out = (float*)d_out;

    const int B = 8, C = 96;
    const int BC = B * C;

    void *p0, *p1, *p2, *p3, *p4, *p5;
    cudaGetSymbolAddress(&p0, g_coeff0);
    cudaGetSymbolAddress(&p1, g_coeff1);
    cudaGetSymbolAddress(&p2, g_ll1);
    cudaGetSymbolAddress(&p3, g_ll2);
    cudaGetSymbolAddress(&p4, g_add1);
    cudaGetSymbolAddress(&p5, g_add0);
    float* coeff0 = (float*)p0;
    float* coeff1 = (float*)p1;
    float* ll1    = (float*)p2;
    float* ll2    = (float*)p3;
    float* add1   = (float*)p4;
    float* add0   = (float*)p5;

    // level 0: x(224) -> coeff0(112) + ll1(112)
    {
        dim3 grid((112 + TX - 1) / TX, (112 + TY - 1) / TY, BC);
        fwd_kernel<true, false><<<grid, 256>>>(
            x, coeff0, ll1, nullptr,
            wconv_w + 0 * 4 * C * 25, wscale + 0 * 4 * C, C, 112, 112);
    }
    // level 1: ll1(112) -> coeff1(56) + ll2(56)
    {
        dim3 grid((56 + TX - 1) / TX, (56 + TY - 1) / TY, BC);
        fwd_kernel<true, false><<<grid, 256>>>(
            ll1, coeff1, ll2, nullptr,
            wconv_w + 1 * 4 * C * 25, wscale + 1 * 4 * C, C, 56, 56);
    }
    // level 2 fwd + inverse fused (next_ll == 0): ll2(56) -> add1(56)
    {
        dim3 grid((28 + TX - 1) / TX, (28 + TY - 1) / TY, BC);
        fwd_kernel<false, true><<<grid, 256>>>(
            ll2, nullptr, nullptr, add1,
            wconv_w + 2 * 4 * C * 25, wscale + 2 * 4 * C, C, 28, 28);
    }
    // inverse level 1: coeff1 (LL += add1) -> add0(112)
    {
        int total2 = BC * 56 * 56 / 2;
        inv_kernel<<<(total2 + 255) / 256, 256>>>(coeff1, add1, add0, 56, 56, total2);
    }
    // final: base conv + ihaar(coeff0, LL += add0) -> out(224)
    {
        dim3 grid(224 / FT, 224 / FT, BC);
        final_kernel<<<grid, 256>>>(x, coeff0, add0, base_w, base_scale,
                                    base_b, out, C, 224, 224);
    }
}